// round 6
// baseline (speedup 1.0000x reference)
#include <cuda_runtime.h>

// -------- Instant-NGP constants --------
#define NLEV 16
#define TSZ  (1u << 19)
#define HMASK (TSZ - 1u)
#define P2 2654435761u
#define P3 805459861u

#define PMAX 393216                 // 2048 * 192 (fixed problem shape)

// scratch: feats laid out as [chunk 0..7][point][float4] — coalesced both ways
__device__ float4 g_feats[8 * PMAX];

// ============================ Kernel A: hash gather ============================
__global__ void __launch_bounds__(256)
ngp_gather_kernel(const float* __restrict__ x,
                  const float* __restrict__ tables, int P)
{
    const int p = blockIdx.x * 256 + threadIdx.x;
    if (p >= P) return;

    const float xf0 = x[3 * p + 0] + 0.5f;
    const float xf1 = x[3 * p + 1] + 0.5f;
    const float xf2 = x[3 * p + 2] + 0.5f;
    const bool inside = (xf0 > 0.f) & (xf0 < 1.f) &
                        (xf1 > 0.f) & (xf1 < 1.f) &
                        (xf2 > 0.f) & (xf2 < 1.f);
    if (!inside) {
        const float4 z = make_float4(0.f, 0.f, 0.f, 0.f);
#pragma unroll
        for (int c = 0; c < 8; c++) g_feats[c * PMAX + p] = z;
        return;
    }

    const float LVL[NLEV] = {16.f, 22.f, 30.f, 42.f, 58.f, 80.f, 111.f, 153.f,
                             212.f, 294.f, 406.f, 561.f, 776.f, 1072.f, 1482.f, 2048.f};
    const float2* __restrict__ tab2 = (const float2*)tables;

    float prevx = 0.f, prevy = 0.f;
#pragma unroll
    for (int l = 0; l < NLEV; l++) {
        const float R = LVL[l];
        const float px = xf0 * R, py = xf1 * R, pz = xf2 * R;
        const float fx = floorf(px), fy = floorf(py), fz = floorf(pz);
        const float frx = px - fx, fry = py - fy, frz = pz - fz;
        const unsigned ux0 = (unsigned)(int)fx;
        const unsigned ux1 = (unsigned)(int)ceilf(px);
        const unsigned uy0 = (unsigned)(int)fy        * P2;
        const unsigned uy1 = (unsigned)(int)ceilf(py) * P2;
        const unsigned uz0 = (unsigned)(int)fz        * P3;
        const unsigned uz1 = (unsigned)(int)ceilf(pz) * P3;
        const float wx0 = 1.f - frx, wy0 = 1.f - fry, wz0 = 1.f - frz;
        const float2* __restrict__ tl = tab2 + (size_t)l * TSZ;
        float ax = 0.f, ay = 0.f;
#pragma unroll
        for (int c = 0; c < 8; c++) {
            unsigned h = ((c & 1) ? ux1 : ux0) ^ ((c & 2) ? uy1 : uy0) ^
                         ((c & 4) ? uz1 : uz0);
            h &= HMASK;
            const float2 v = __ldg(&tl[h]);
            const float w = ((c & 1) ? frx : wx0) * ((c & 2) ? fry : wy0) *
                            ((c & 4) ? frz : wz0);
            ax = fmaf(w, v.x, ax);
            ay = fmaf(w, v.y, ay);
        }
        if (l & 1) {
            g_feats[(l >> 1) * PMAX + p] = make_float4(prevx, prevy, ax, ay);
        } else {
            prevx = ax; prevy = ay;
        }
    }
}

// ============================ Kernel B: fused MLPs ============================
// SMEM weight layout (float offsets)
#define OFF_DW1 0      // 32*64 = 2048
#define OFF_DB1 2048   // 64
#define OFF_DW2 2112   // 64*16 = 1024
#define OFF_DB2 3136   // 16
#define OFF_CW1 3152   // 43*64 = 2752
#define OFF_CB1 5904   // 64
#define OFF_CW2 5968   // 64*64 = 4096
#define OFF_CB2 10064  // 64
#define OFF_CW3 10128  // 64*3 = 192
#define OFF_CB3 10320  // 3
#define W_PAD   10324  // 41,296 bytes

__global__ void __launch_bounds__(128, 4)
ngp_mlp_kernel(const float* __restrict__ x,
               const float* __restrict__ rdir,
               const float* __restrict__ dW1, const float* __restrict__ db1,
               const float* __restrict__ dW2, const float* __restrict__ db2,
               const float* __restrict__ cW1, const float* __restrict__ cb1,
               const float* __restrict__ cW2, const float* __restrict__ cb2,
               const float* __restrict__ cW3, const float* __restrict__ cb3,
               float* __restrict__ out, int P)
{
    __shared__ float sW[W_PAD];
    const int tid = threadIdx.x;
    {
        for (int i = tid; i < 2048; i += 128) sW[OFF_DW1 + i] = dW1[i];
        for (int i = tid; i < 64;   i += 128) sW[OFF_DB1 + i] = db1[i];
        for (int i = tid; i < 1024; i += 128) sW[OFF_DW2 + i] = dW2[i];
        for (int i = tid; i < 16;   i += 128) sW[OFF_DB2 + i] = db2[i];
        for (int i = tid; i < 2752; i += 128) sW[OFF_CW1 + i] = cW1[i];
        for (int i = tid; i < 64;   i += 128) sW[OFF_CB1 + i] = cb1[i];
        for (int i = tid; i < 4096; i += 128) sW[OFF_CW2 + i] = cW2[i];
        for (int i = tid; i < 64;   i += 128) sW[OFF_CB2 + i] = cb2[i];
        for (int i = tid; i < 192;  i += 128) sW[OFF_CW3 + i] = cW3[i];
        for (int i = tid; i < 3;    i += 128) sW[OFF_CB3 + i] = cb3[i];
    }
    __syncthreads();

    const int p = blockIdx.x * 128 + tid;
    if (p >= P) return;

    // recompute mask (3 coalesced loads — cheaper than carrying a flag buffer)
    const float xf0 = x[3 * p + 0] + 0.5f;
    const float xf1 = x[3 * p + 1] + 0.5f;
    const float xf2 = x[3 * p + 2] + 0.5f;
    const bool inside = (xf0 > 0.f) & (xf0 < 1.f) &
                        (xf1 > 0.f) & (xf1 < 1.f) &
                        (xf2 > 0.f) & (xf2 < 1.f);

    // ---- density layer 1: acc[64] = feats @ dW1 + db1 (feats streamed) ----
    float acc[64];
#pragma unroll
    for (int j = 0; j < 16; j++) {
        const float4 b = *(const float4*)(sW + OFF_DB1 + 4 * j);
        acc[4 * j + 0] = b.x; acc[4 * j + 1] = b.y;
        acc[4 * j + 2] = b.z; acc[4 * j + 3] = b.w;
    }
#pragma unroll
    for (int c = 0; c < 8; c++) {
        const float4 f = __ldg(&g_feats[c * PMAX + p]);
        const float fa[4] = {f.x, f.y, f.z, f.w};
#pragma unroll
        for (int i = 0; i < 4; i++) {
            const float a = fa[i];
            const float4* __restrict__ w =
                (const float4*)(sW + OFF_DW1 + (4 * c + i) * 64);
#pragma unroll
            for (int j = 0; j < 16; j++) {
                const float4 wv = w[j];
                acc[4 * j + 0] = fmaf(a, wv.x, acc[4 * j + 0]);
                acc[4 * j + 1] = fmaf(a, wv.y, acc[4 * j + 1]);
                acc[4 * j + 2] = fmaf(a, wv.z, acc[4 * j + 2]);
                acc[4 * j + 3] = fmaf(a, wv.w, acc[4 * j + 3]);
            }
        }
    }
#pragma unroll
    for (int j = 0; j < 64; j++) acc[j] = fmaxf(acc[j], 0.f);   // acc == h1

    // ---- density layer 2: ls[16] = h1 @ dW2 + db2 ----
    float ls[16];
#pragma unroll
    for (int j = 0; j < 4; j++) {
        const float4 b = *(const float4*)(sW + OFF_DB2 + 4 * j);
        ls[4 * j + 0] = b.x; ls[4 * j + 1] = b.y;
        ls[4 * j + 2] = b.z; ls[4 * j + 3] = b.w;
    }
#pragma unroll
    for (int k = 0; k < 64; k++) {
        const float a = acc[k];
        const float4* __restrict__ w = (const float4*)(sW + OFF_DW2 + k * 16);
#pragma unroll
        for (int j = 0; j < 4; j++) {
            const float4 wv = w[j];
            ls[4 * j + 0] = fmaf(a, wv.x, ls[4 * j + 0]);
            ls[4 * j + 1] = fmaf(a, wv.y, ls[4 * j + 1]);
            ls[4 * j + 2] = fmaf(a, wv.z, ls[4 * j + 2]);
            ls[4 * j + 3] = fmaf(a, wv.w, ls[4 * j + 3]);
        }
    }
    const float ls0 = ls[0];

    // ---- color-MLP input cin[43] = [log_sigma(16), rd(3), PE(24)] ----
    float cin[43];
#pragma unroll
    for (int k = 0; k < 16; k++) cin[k] = ls[k];
    {
        const float r0 = rdir[3 * p + 0];
        const float r1 = rdir[3 * p + 1];
        const float r2 = rdir[3 * p + 2];
        cin[16] = r0; cin[17] = r1; cin[18] = r2;
        const float rv[3] = {r0, r1, r2};
#pragma unroll
        for (int d = 0; d < 3; d++) {
#pragma unroll
            for (int l = 0; l < 4; l++) {
                float s, c;
                __sincosf(rv[d] * (6.283185307179586f * (float)(1 << l)), &s, &c);
                cin[19 + d * 8 + l]     = s;
                cin[19 + d * 8 + 4 + l] = c;
            }
        }
    }

    // ---- color layer 1 (full-width acc, peak live = acc64 + cin43) ----
#pragma unroll
    for (int j = 0; j < 16; j++) {
        const float4 b = *(const float4*)(sW + OFF_CB1 + 4 * j);
        acc[4 * j + 0] = b.x; acc[4 * j + 1] = b.y;
        acc[4 * j + 2] = b.z; acc[4 * j + 3] = b.w;
    }
#pragma unroll
    for (int k = 0; k < 43; k++) {
        const float a = cin[k];
        const float4* __restrict__ w = (const float4*)(sW + OFF_CW1 + k * 64);
#pragma unroll
        for (int j = 0; j < 16; j++) {
            const float4 wv = w[j];
            acc[4 * j + 0] = fmaf(a, wv.x, acc[4 * j + 0]);
            acc[4 * j + 1] = fmaf(a, wv.y, acc[4 * j + 1]);
            acc[4 * j + 2] = fmaf(a, wv.z, acc[4 * j + 2]);
            acc[4 * j + 3] = fmaf(a, wv.w, acc[4 * j + 3]);
        }
    }
#pragma unroll
    for (int j = 0; j < 64; j++) acc[j] = fmaxf(acc[j], 0.f);   // acc == h

    // ---- color layers 2+3 fused, j-blocked by 32 ----
    float c0 = sW[OFF_CB3 + 0], c1 = sW[OFF_CB3 + 1], c2 = sW[OFF_CB3 + 2];
#pragma unroll
    for (int jb = 0; jb < 2; jb++) {
        float acc2[32];
#pragma unroll
        for (int j = 0; j < 8; j++) {
            const float4 b = *(const float4*)(sW + OFF_CB2 + jb * 32 + 4 * j);
            acc2[4 * j + 0] = b.x; acc2[4 * j + 1] = b.y;
            acc2[4 * j + 2] = b.z; acc2[4 * j + 3] = b.w;
        }
#pragma unroll
        for (int k = 0; k < 64; k++) {
            const float a = acc[k];
            const float4* __restrict__ w =
                (const float4*)(sW + OFF_CW2 + k * 64 + jb * 32);
#pragma unroll
            for (int j = 0; j < 8; j++) {
                const float4 wv = w[j];
                acc2[4 * j + 0] = fmaf(a, wv.x, acc2[4 * j + 0]);
                acc2[4 * j + 1] = fmaf(a, wv.y, acc2[4 * j + 1]);
                acc2[4 * j + 2] = fmaf(a, wv.z, acc2[4 * j + 2]);
                acc2[4 * j + 3] = fmaf(a, wv.w, acc2[4 * j + 3]);
            }
        }
#pragma unroll
        for (int j = 0; j < 32; j++) {
            const float v = fmaxf(acc2[j], 0.f);
            const int idx = jb * 32 + j;
            c0 = fmaf(v, sW[OFF_CW3 + idx * 3 + 0], c0);
            c1 = fmaf(v, sW[OFF_CW3 + idx * 3 + 1], c1);
            c2 = fmaf(v, sW[OFF_CW3 + idx * 3 + 2], c2);
        }
    }

    float o0 = 1.f / (1.f + __expf(-c0));
    float o1 = 1.f / (1.f + __expf(-c1));
    float o2 = 1.f / (1.f + __expf(-c2));
    float sg = __expf(ls0);
    if (!inside) { o0 = 0.f; o1 = 0.f; o2 = 0.f; sg = 0.f; }

    out[3 * p + 0] = o0;
    out[3 * p + 1] = o1;
    out[3 * p + 2] = o2;
    out[3 * P + p] = sg;
}

extern "C" void kernel_launch(void* const* d_in, const int* in_sizes, int n_in,
                              void* d_out, int out_size)
{
    (void)n_in; (void)out_size;
    const float* x      = (const float*)d_in[0];
    const float* rdir   = (const float*)d_in[1];
    const float* tables = (const float*)d_in[2];
    const float* dW1    = (const float*)d_in[3];
    const float* db1    = (const float*)d_in[4];
    const float* dW2    = (const float*)d_in[5];
    const float* db2    = (const float*)d_in[6];
    const float* cW1    = (const float*)d_in[7];
    const float* cb1    = (const float*)d_in[8];
    const float* cW2    = (const float*)d_in[9];
    const float* cb2    = (const float*)d_in[10];
    const float* cW3    = (const float*)d_in[11];
    const float* cb3    = (const float*)d_in[12];
    float* out = (float*)d_out;

    const int P = in_sizes[0] / 3;          // 393216

    ngp_gather_kernel<<<(P + 255) / 256, 256>>>(x, tables, P);
    ngp_mlp_kernel<<<(P + 127) / 128, 128>>>(
        x, rdir, dW1, db1, dW2, db2,
        cW1, cb1, cW2, cb2, cW3, cb3, out, P);
}

// round 7
// speedup vs baseline: 1.2272x; 1.2272x over previous
#include <cuda_runtime.h>

// -------- Instant-NGP constants --------
#define NLEV 16
#define TSZ  (1u << 19)
#define HMASK (TSZ - 1u)
#define P2 2654435761u
#define P3 805459861u

#define PMAX 393216                 // 2048 * 192 (fixed problem shape)

// scratch: feats laid out as [chunk 0..7][point][float4] — coalesced both ways
__device__ float4 g_feats[8 * PMAX];

// ---- packed f32x2 helpers (sm_103a FFMA2 — PTX-only, ptxas never auto-fuses) ----
typedef unsigned long long u64t;
__device__ __forceinline__ void ffma2(u64t& d, u64t a2, u64t b2) {
    asm("fma.rn.f32x2 %0, %1, %2, %0;" : "+l"(d) : "l"(a2), "l"(b2));
}
__device__ __forceinline__ u64t dup2(float a) {
    u64t r; unsigned ai = __float_as_uint(a);
    asm("mov.b64 %0, {%1, %1};" : "=l"(r) : "r"(ai));
    return r;
}
__device__ __forceinline__ void unpack2(u64t v, float& lo, float& hi) {
    unsigned l, h;
    asm("mov.b64 {%0, %1}, %2;" : "=r"(l), "=r"(h) : "l"(v));
    lo = __uint_as_float(l); hi = __uint_as_float(h);
}

// ============================ Kernel A: hash gather ============================
__global__ void __launch_bounds__(256)
ngp_gather_kernel(const float* __restrict__ x,
                  const float* __restrict__ tables, int P)
{
    const int p = blockIdx.x * 256 + threadIdx.x;
    if (p >= P) return;

    const float xf0 = x[3 * p + 0] + 0.5f;
    const float xf1 = x[3 * p + 1] + 0.5f;
    const float xf2 = x[3 * p + 2] + 0.5f;
    const bool inside = (xf0 > 0.f) & (xf0 < 1.f) &
                        (xf1 > 0.f) & (xf1 < 1.f) &
                        (xf2 > 0.f) & (xf2 < 1.f);
    if (!inside) {
        const float4 z = make_float4(0.f, 0.f, 0.f, 0.f);
#pragma unroll
        for (int c = 0; c < 8; c++) g_feats[c * PMAX + p] = z;
        return;
    }

    const float LVL[NLEV] = {16.f, 22.f, 30.f, 42.f, 58.f, 80.f, 111.f, 153.f,
                             212.f, 294.f, 406.f, 561.f, 776.f, 1072.f, 1482.f, 2048.f};
    const float2* __restrict__ tab2 = (const float2*)tables;

    float prevx = 0.f, prevy = 0.f;
#pragma unroll
    for (int l = 0; l < NLEV; l++) {
        const float R = LVL[l];
        const float px = xf0 * R, py = xf1 * R, pz = xf2 * R;
        const float fx = floorf(px), fy = floorf(py), fz = floorf(pz);
        const float frx = px - fx, fry = py - fy, frz = pz - fz;
        const unsigned ux0 = (unsigned)(int)fx;
        const unsigned ux1 = (unsigned)(int)ceilf(px);
        const unsigned uy0 = (unsigned)(int)fy        * P2;
        const unsigned uy1 = (unsigned)(int)ceilf(py) * P2;
        const unsigned uz0 = (unsigned)(int)fz        * P3;
        const unsigned uz1 = (unsigned)(int)ceilf(pz) * P3;
        const float wx0 = 1.f - frx, wy0 = 1.f - fry, wz0 = 1.f - frz;
        const float2* __restrict__ tl = tab2 + (size_t)l * TSZ;
        float ax = 0.f, ay = 0.f;
#pragma unroll
        for (int c = 0; c < 8; c++) {
            unsigned h = ((c & 1) ? ux1 : ux0) ^ ((c & 2) ? uy1 : uy0) ^
                         ((c & 4) ? uz1 : uz0);
            h &= HMASK;
            const float2 v = __ldg(&tl[h]);
            const float w = ((c & 1) ? frx : wx0) * ((c & 2) ? fry : wy0) *
                            ((c & 4) ? frz : wz0);
            ax = fmaf(w, v.x, ax);
            ay = fmaf(w, v.y, ay);
        }
        if (l & 1) {
            g_feats[(l >> 1) * PMAX + p] = make_float4(prevx, prevy, ax, ay);
        } else {
            prevx = ax; prevy = ay;
        }
    }
}

// ============================ Kernel B: fused MLPs (f32x2 packed) ============================
// SMEM weight layout (float offsets) — all 8-/16-byte aligned
#define OFF_DW1 0      // 32*64 = 2048
#define OFF_DB1 2048   // 64
#define OFF_DW2 2112   // 64*16 = 1024
#define OFF_DB2 3136   // 16
#define OFF_CW1 3152   // 43*64 = 2752
#define OFF_CB1 5904   // 64
#define OFF_CW2 5968   // 64*64 = 4096
#define OFF_CB2 10064  // 64
#define OFF_CW3 10128  // 64*3 = 192
#define OFF_CB3 10320  // 3
#define W_PAD   10324  // 41,296 bytes

__global__ void __launch_bounds__(128, 4)
ngp_mlp_kernel(const float* __restrict__ x,
               const float* __restrict__ rdir,
               const float* __restrict__ dW1, const float* __restrict__ db1,
               const float* __restrict__ dW2, const float* __restrict__ db2,
               const float* __restrict__ cW1, const float* __restrict__ cb1,
               const float* __restrict__ cW2, const float* __restrict__ cb2,
               const float* __restrict__ cW3, const float* __restrict__ cb3,
               float* __restrict__ out, int P)
{
    __shared__ __align__(16) float sW[W_PAD];
    const int tid = threadIdx.x;
    {
        for (int i = tid; i < 2048; i += 128) sW[OFF_DW1 + i] = dW1[i];
        for (int i = tid; i < 64;   i += 128) sW[OFF_DB1 + i] = db1[i];
        for (int i = tid; i < 1024; i += 128) sW[OFF_DW2 + i] = dW2[i];
        for (int i = tid; i < 16;   i += 128) sW[OFF_DB2 + i] = db2[i];
        for (int i = tid; i < 2752; i += 128) sW[OFF_CW1 + i] = cW1[i];
        for (int i = tid; i < 64;   i += 128) sW[OFF_CB1 + i] = cb1[i];
        for (int i = tid; i < 4096; i += 128) sW[OFF_CW2 + i] = cW2[i];
        for (int i = tid; i < 64;   i += 128) sW[OFF_CB2 + i] = cb2[i];
        for (int i = tid; i < 192;  i += 128) sW[OFF_CW3 + i] = cW3[i];
        for (int i = tid; i < 3;    i += 128) sW[OFF_CB3 + i] = cb3[i];
    }
    __syncthreads();

    const int p = blockIdx.x * 128 + tid;
    if (p >= P) return;

    const float xf0 = x[3 * p + 0] + 0.5f;
    const float xf1 = x[3 * p + 1] + 0.5f;
    const float xf2 = x[3 * p + 2] + 0.5f;
    const bool inside = (xf0 > 0.f) & (xf0 < 1.f) &
                        (xf1 > 0.f) & (xf1 < 1.f) &
                        (xf2 > 0.f) & (xf2 < 1.f);

    // ---- density layer 1: acc2[32] (pairs of outputs) = feats @ dW1 + db1 ----
    u64t acc2[32];
    {
        const u64t* __restrict__ b = (const u64t*)(sW + OFF_DB1);
#pragma unroll
        for (int j = 0; j < 32; j++) acc2[j] = b[j];
    }
#pragma unroll
    for (int c = 0; c < 8; c++) {
        const float4 f = __ldg(&g_feats[c * PMAX + p]);
        const float fa[4] = {f.x, f.y, f.z, f.w};
#pragma unroll
        for (int i = 0; i < 4; i++) {
            const u64t a2 = dup2(fa[i]);
            const u64t* __restrict__ w = (const u64t*)(sW + OFF_DW1 + (4 * c + i) * 64);
#pragma unroll
            for (int j = 0; j < 32; j++) ffma2(acc2[j], a2, w[j]);
        }
    }
    float h1[64];
#pragma unroll
    for (int j = 0; j < 32; j++) {
        float lo, hi; unpack2(acc2[j], lo, hi);
        h1[2 * j + 0] = fmaxf(lo, 0.f);
        h1[2 * j + 1] = fmaxf(hi, 0.f);
    }

    // ---- density layer 2: ls[16] = h1 @ dW2 + db2 (packed pairs) ----
    u64t lsa[8];
    {
        const u64t* __restrict__ b = (const u64t*)(sW + OFF_DB2);
#pragma unroll
        for (int j = 0; j < 8; j++) lsa[j] = b[j];
    }
#pragma unroll
    for (int k = 0; k < 64; k++) {
        const u64t a2 = dup2(h1[k]);
        const u64t* __restrict__ w = (const u64t*)(sW + OFF_DW2 + k * 16);
#pragma unroll
        for (int j = 0; j < 8; j++) ffma2(lsa[j], a2, w[j]);
    }
    float ls[16];
#pragma unroll
    for (int j = 0; j < 8; j++) unpack2(lsa[j], ls[2 * j], ls[2 * j + 1]);
    const float ls0 = ls[0];

    // ---- color-MLP input cin[43] = [log_sigma(16), rd(3), PE(24)] ----
    float cin[43];
#pragma unroll
    for (int k = 0; k < 16; k++) cin[k] = ls[k];
    {
        const float r0 = rdir[3 * p + 0];
        const float r1 = rdir[3 * p + 1];
        const float r2 = rdir[3 * p + 2];
        cin[16] = r0; cin[17] = r1; cin[18] = r2;
        const float rv[3] = {r0, r1, r2};
#pragma unroll
        for (int d = 0; d < 3; d++) {
#pragma unroll
            for (int l = 0; l < 4; l++) {
                float s, c;
                __sincosf(rv[d] * (6.283185307179586f * (float)(1 << l)), &s, &c);
                cin[19 + d * 8 + l]     = s;
                cin[19 + d * 8 + 4 + l] = c;
            }
        }
    }

    // ---- color layer 1: acc2[32] = cin @ cW1 + cb1 ----
    {
        const u64t* __restrict__ b = (const u64t*)(sW + OFF_CB1);
#pragma unroll
        for (int j = 0; j < 32; j++) acc2[j] = b[j];
    }
#pragma unroll
    for (int k = 0; k < 43; k++) {
        const u64t a2 = dup2(cin[k]);
        const u64t* __restrict__ w = (const u64t*)(sW + OFF_CW1 + k * 64);
#pragma unroll
        for (int j = 0; j < 32; j++) ffma2(acc2[j], a2, w[j]);
    }
    float h[64];
#pragma unroll
    for (int j = 0; j < 32; j++) {
        float lo, hi; unpack2(acc2[j], lo, hi);
        h[2 * j + 0] = fmaxf(lo, 0.f);
        h[2 * j + 1] = fmaxf(hi, 0.f);
    }

    // ---- color layers 2+3 fused, j-blocked by 32 outputs (16 pairs) ----
    float c0 = sW[OFF_CB3 + 0], c1 = sW[OFF_CB3 + 1], c2 = sW[OFF_CB3 + 2];
#pragma unroll
    for (int jb = 0; jb < 2; jb++) {
        u64t a2b[16];
        {
            const u64t* __restrict__ b = (const u64t*)(sW + OFF_CB2 + jb * 32);
#pragma unroll
            for (int j = 0; j < 16; j++) a2b[j] = b[j];
        }
#pragma unroll
        for (int k = 0; k < 64; k++) {
            const u64t a2 = dup2(h[k]);
            const u64t* __restrict__ w = (const u64t*)(sW + OFF_CW2 + k * 64 + jb * 32);
#pragma unroll
            for (int j = 0; j < 16; j++) ffma2(a2b[j], a2, w[j]);
        }
#pragma unroll
        for (int j = 0; j < 16; j++) {
            float lo, hi; unpack2(a2b[j], lo, hi);
            const float v0 = fmaxf(lo, 0.f);
            const float v1 = fmaxf(hi, 0.f);
            const int idx = jb * 32 + 2 * j;
            c0 = fmaf(v0, sW[OFF_CW3 + idx * 3 + 0], c0);
            c1 = fmaf(v0, sW[OFF_CW3 + idx * 3 + 1], c1);
            c2 = fmaf(v0, sW[OFF_CW3 + idx * 3 + 2], c2);
            c0 = fmaf(v1, sW[OFF_CW3 + idx * 3 + 3], c0);
            c1 = fmaf(v1, sW[OFF_CW3 + idx * 3 + 4], c1);
            c2 = fmaf(v1, sW[OFF_CW3 + idx * 3 + 5], c2);
        }
    }

    float o0 = 1.f / (1.f + __expf(-c0));
    float o1 = 1.f / (1.f + __expf(-c1));
    float o2 = 1.f / (1.f + __expf(-c2));
    float sg = __expf(ls0);
    if (!inside) { o0 = 0.f; o1 = 0.f; o2 = 0.f; sg = 0.f; }

    out[3 * p + 0] = o0;
    out[3 * p + 1] = o1;
    out[3 * p + 2] = o2;
    out[3 * P + p] = sg;
}

extern "C" void kernel_launch(void* const* d_in, const int* in_sizes, int n_in,
                              void* d_out, int out_size)
{
    (void)n_in; (void)out_size;
    const float* x      = (const float*)d_in[0];
    const float* rdir   = (const float*)d_in[1];
    const float* tables = (const float*)d_in[2];
    const float* dW1    = (const float*)d_in[3];
    const float* db1    = (const float*)d_in[4];
    const float* dW2    = (const float*)d_in[5];
    const float* db2    = (const float*)d_in[6];
    const float* cW1    = (const float*)d_in[7];
    const float* cb1    = (const float*)d_in[8];
    const float* cW2    = (const float*)d_in[9];
    const float* cb2    = (const float*)d_in[10];
    const float* cW3    = (const float*)d_in[11];
    const float* cb3    = (const float*)d_in[12];
    float* out = (float*)d_out;

    const int P = in_sizes[0] / 3;          // 393216

    ngp_gather_kernel<<<(P + 255) / 256, 256>>>(x, tables, P);
    ngp_mlp_kernel<<<(P + 127) / 128, 128>>>(
        x, rdir, dW1, db1, dW2, db2,
        cW1, cb1, cW2, cb2, cW3, cb3, out, P);
}